// round 1
// baseline (speedup 1.0000x reference)
#include <cuda_runtime.h>
#include <math.h>
#include <stdint.h>

#define BATCH 32
#define SEQ   2048
#define DIM   512
#define DADIM 512
#define NLDIM 512

// Scratch for w = tanh(x @ W1^T): [B, L, DA] fp32 = 128 MiB (static, allocation-free)
__device__ float g_w[(size_t)BATCH * SEQ * DADIM];

// ---------------------------------------------------------------------------
// NT GEMM: C[m,n] = (opt tanh)( sum_k A[m,k] * B[n,k] )
// A: [M,K] row-major, B: [N,K] row-major, C: [M,N] row-major.
// 64x64 tile, BK=16, 256 threads, 4x4 per thread. Batched via blockIdx.z.
// ---------------------------------------------------------------------------
__global__ __launch_bounds__(256) void gemm_nt(
    const float* __restrict__ A, long long sA,
    const float* __restrict__ B, long long sB,
    float* __restrict__ C, long long sC,
    int M, int N, int K, int do_tanh)
{
    const float* Ab = A + (size_t)blockIdx.z * sA;
    const float* Bb = B + (size_t)blockIdx.z * sB;
    float*       Cb = C + (size_t)blockIdx.z * sC;

    __shared__ float As[16][64];
    __shared__ float Bs[16][64];

    const int t  = threadIdx.x;
    const int m0 = blockIdx.y * 64;
    const int n0 = blockIdx.x * 64;
    const int lr = t >> 2;          // 0..63 row within tile
    const int lk = (t & 3) * 4;     // 0,4,8,12 k-quad
    const int ty = t >> 4;          // 0..15
    const int tx = t & 15;          // 0..15

    float acc[4][4] = {};

    for (int k0 = 0; k0 < K; k0 += 16) {
        float4 a4 = *(const float4*)(Ab + (size_t)(m0 + lr) * K + k0 + lk);
        float4 b4 = *(const float4*)(Bb + (size_t)(n0 + lr) * K + k0 + lk);
        As[lk + 0][lr] = a4.x; As[lk + 1][lr] = a4.y;
        As[lk + 2][lr] = a4.z; As[lk + 3][lr] = a4.w;
        Bs[lk + 0][lr] = b4.x; Bs[lk + 1][lr] = b4.y;
        Bs[lk + 2][lr] = b4.z; Bs[lk + 3][lr] = b4.w;
        __syncthreads();
#pragma unroll
        for (int k = 0; k < 16; k++) {
            float4 av = *(const float4*)&As[k][ty * 4];
            float4 bv = *(const float4*)&Bs[k][tx * 4];
            float ar[4] = {av.x, av.y, av.z, av.w};
            float br[4] = {bv.x, bv.y, bv.z, bv.w};
#pragma unroll
            for (int i = 0; i < 4; i++)
#pragma unroll
                for (int j = 0; j < 4; j++)
                    acc[i][j] += ar[i] * br[j];
        }
        __syncthreads();
    }

#pragma unroll
    for (int i = 0; i < 4; i++) {
        float4 o;
        if (do_tanh) {
            o.x = tanhf(acc[i][0]); o.y = tanhf(acc[i][1]);
            o.z = tanhf(acc[i][2]); o.w = tanhf(acc[i][3]);
        } else {
            o.x = acc[i][0]; o.y = acc[i][1];
            o.z = acc[i][2]; o.w = acc[i][3];
        }
        *(float4*)(Cb + (size_t)(m0 + ty * 4 + i) * N + n0 + tx * 4) = o;
    }
}

// ---------------------------------------------------------------------------
// NN GEMM: C[m,n] = sum_k A[m,k] * B[k,n]
// A: [M,K] row-major, B: [K,N] row-major. Batched via blockIdx.z.
// ---------------------------------------------------------------------------
__global__ __launch_bounds__(256) void gemm_nn(
    const float* __restrict__ A, long long sA,
    const float* __restrict__ B, long long sB,
    float* __restrict__ C, long long sC,
    int M, int N, int K)
{
    const float* Ab = A + (size_t)blockIdx.z * sA;
    const float* Bb = B + (size_t)blockIdx.z * sB;
    float*       Cb = C + (size_t)blockIdx.z * sC;

    __shared__ float As[16][64];
    __shared__ float Bs[16][64];

    const int t  = threadIdx.x;
    const int m0 = blockIdx.y * 64;
    const int n0 = blockIdx.x * 64;
    const int lr  = t >> 2;         // A: row within tile
    const int lk  = (t & 3) * 4;    // A: k-quad
    const int br_ = t >> 4;         // B: k row 0..15
    const int bc  = (t & 15) * 4;   // B: col quad
    const int ty = t >> 4;
    const int tx = t & 15;

    float acc[4][4] = {};

    for (int k0 = 0; k0 < K; k0 += 16) {
        float4 a4 = *(const float4*)(Ab + (size_t)(m0 + lr) * K + k0 + lk);
        As[lk + 0][lr] = a4.x; As[lk + 1][lr] = a4.y;
        As[lk + 2][lr] = a4.z; As[lk + 3][lr] = a4.w;
        float4 b4 = *(const float4*)(Bb + (size_t)(k0 + br_) * N + n0 + bc);
        *(float4*)&Bs[br_][bc] = b4;
        __syncthreads();
#pragma unroll
        for (int k = 0; k < 16; k++) {
            float4 av = *(const float4*)&As[k][ty * 4];
            float4 bv = *(const float4*)&Bs[k][tx * 4];
            float ar[4] = {av.x, av.y, av.z, av.w};
            float br2[4] = {bv.x, bv.y, bv.z, bv.w};
#pragma unroll
            for (int i = 0; i < 4; i++)
#pragma unroll
                for (int j = 0; j < 4; j++)
                    acc[i][j] += ar[i] * br2[j];
        }
        __syncthreads();
    }

#pragma unroll
    for (int i = 0; i < 4; i++) {
        float4 o = make_float4(acc[i][0], acc[i][1], acc[i][2], acc[i][3]);
        *(float4*)(Cb + (size_t)(m0 + ty * 4 + i) * N + n0 + tx * 4) = o;
    }
}

// ---------------------------------------------------------------------------
// Row softmax, in place. One block per row of length SEQ (2048). 256 threads.
// ---------------------------------------------------------------------------
__global__ __launch_bounds__(256) void softmax_rows(float* __restrict__ d)
{
    float* p = d + (size_t)blockIdx.x * SEQ;
    const int t = threadIdx.x;
    const int w = t >> 5, lane = t & 31;

    float v[8];
    float m = -1e30f;
#pragma unroll
    for (int k = 0; k < 8; k++) {
        v[k] = p[t + k * 256];
        m = fmaxf(m, v[k]);
    }
#pragma unroll
    for (int o = 16; o; o >>= 1) m = fmaxf(m, __shfl_xor_sync(0xffffffffu, m, o));

    __shared__ float sm[8];
    __shared__ float ss[8];
    if (lane == 0) sm[w] = m;
    __syncthreads();
    float bm = sm[0];
#pragma unroll
    for (int i = 1; i < 8; i++) bm = fmaxf(bm, sm[i]);

    float s = 0.f;
#pragma unroll
    for (int k = 0; k < 8; k++) {
        v[k] = __expf(v[k] - bm);
        s += v[k];
    }
#pragma unroll
    for (int o = 16; o; o >>= 1) s += __shfl_xor_sync(0xffffffffu, s, o);
    if (lane == 0) ss[w] = s;
    __syncthreads();
    float bs = 0.f;
#pragma unroll
    for (int i = 0; i < 8; i++) bs += ss[i];
    float inv = 1.0f / bs;
#pragma unroll
    for (int k = 0; k < 8; k++) p[t + k * 256] = v[k] * inv;
}

// ---------------------------------------------------------------------------
// weighted_output[r] = dot(ctx[r, :], W3[r % NL, :]) + b3[r % NL]
// one warp per row (r in [0, B*NL)), 8 warps per block.
// ---------------------------------------------------------------------------
__global__ __launch_bounds__(256) void weighted_out(
    const float* __restrict__ ctx, const float* __restrict__ W3,
    const float* __restrict__ b3, float* __restrict__ out)
{
    const int r    = blockIdx.x * 8 + (threadIdx.x >> 5);
    const int lane = threadIdx.x & 31;
    const int n    = r & (NLDIM - 1);

    const float* c = ctx + (size_t)r * DIM;
    const float* w = W3  + (size_t)n * DIM;

    float s = 0.f;
#pragma unroll
    for (int j = 0; j < 4; j++) {
        float4 cv = *(const float4*)(c + lane * 4 + j * 128);
        float4 wv = *(const float4*)(w + lane * 4 + j * 128);
        s += cv.x * wv.x + cv.y * wv.y + cv.z * wv.z + cv.w * wv.w;
    }
#pragma unroll
    for (int o = 16; o; o >>= 1) s += __shfl_xor_sync(0xffffffffu, s, o);
    if (lane == 0) out[r] = s + b3[n];
}

// ---------------------------------------------------------------------------
extern "C" void kernel_launch(void* const* d_in, const int* in_sizes, int n_in,
                              void* d_out, int out_size)
{
    const float* x  = (const float*)d_in[0];  // [B, L, D]
    const float* W1 = (const float*)d_in[1];  // [DA, D]
    const float* W2 = (const float*)d_in[2];  // [NL, DA]
    const float* W3 = (const float*)d_in[3];  // [NL, D]
    const float* b3 = (const float*)d_in[4];  // [NL]

    // Output tuple layout (flattened, in reference return order):
    float* ctx = (float*)d_out;                              // [B, NL, D]
    float* wo  = ctx + (size_t)BATCH * NLDIM * DIM;          // [B, NL]
    float* att = wo  + (size_t)BATCH * NLDIM;                // [B, NL, L]

    float* wbuf = nullptr;
    cudaGetSymbolAddress((void**)&wbuf, g_w);

    // 1) w = tanh(x @ W1^T) : [B*L, DA]   (M=65536, N=512, K=512)
    {
        dim3 grid(DADIM / 64, (BATCH * SEQ) / 64, 1);
        gemm_nt<<<grid, 256>>>(x, 0, W1, 0, wbuf, 0,
                               BATCH * SEQ, DADIM, DIM, 1);
    }

    // 2) logits^T written directly into att layout: att[b,n,l] = sum_a W2[n,a]*w[b,l,a]
    //    per-batch NT GEMM: M=NL, N=L, K=DA
    {
        dim3 grid(SEQ / 64, NLDIM / 64, BATCH);
        gemm_nt<<<grid, 256>>>(W2, 0,
                               wbuf, (long long)SEQ * DADIM,
                               att, (long long)NLDIM * SEQ,
                               NLDIM, SEQ, DADIM, 0);
    }

    // 3) softmax over L, in place on att rows: B*NL rows of length SEQ
    softmax_rows<<<BATCH * NLDIM, 256>>>(att);

    // 4) context[b,n,d] = sum_l att[b,n,l] * x[b,l,d]
    //    per-batch NN GEMM: M=NL, N=D, K=L
    {
        dim3 grid(DIM / 64, NLDIM / 64, BATCH);
        gemm_nn<<<grid, 256>>>(att, (long long)NLDIM * SEQ,
                               x, (long long)SEQ * DIM,
                               ctx, (long long)NLDIM * DIM,
                               NLDIM, DIM, SEQ);
    }

    // 5) weighted_output = rowwise dot(ctx, W3) + b3
    weighted_out<<<(BATCH * NLDIM) / 8, 256>>>(ctx, W3, b3, wo);
}

// round 3
// speedup vs baseline: 2.5735x; 2.5735x over previous
#include <cuda_runtime.h>
#include <cuda_bf16.h>
#include <math.h>
#include <stdint.h>

#define BATCH 32
#define SEQ   2048
#define DIM   512
#define DADIM 512
#define NLDIM 512

// ---------------- split scratch (static, allocation-free) ----------------
__device__ __nv_bfloat16 g_xhi [(size_t)BATCH * SEQ * DIM];
__device__ __nv_bfloat16 g_xlo [(size_t)BATCH * SEQ * DIM];
__device__ __nv_bfloat16 g_xthi[(size_t)BATCH * DIM * SEQ];   // per-batch x^T
__device__ __nv_bfloat16 g_xtlo[(size_t)BATCH * DIM * SEQ];
__device__ __nv_bfloat16 g_whi [(size_t)BATCH * SEQ * DADIM]; // tanh output split
__device__ __nv_bfloat16 g_wlo [(size_t)BATCH * SEQ * DADIM];
__device__ __nv_bfloat16 g_ahi [(size_t)BATCH * NLDIM * SEQ]; // softmax output split
__device__ __nv_bfloat16 g_alo [(size_t)BATCH * NLDIM * SEQ];
__device__ __nv_bfloat16 g_w1hi[DADIM * DIM], g_w1lo[DADIM * DIM];
__device__ __nv_bfloat16 g_w2hi[NLDIM * DADIM], g_w2lo[NLDIM * DADIM];

// ---------------- PTX helpers (family-portable only: no tcgen05) ----------
__device__ __forceinline__ uint32_t smem_u32(const void* p) {
    uint32_t a;
    asm("{ .reg .u64 t; cvta.to.shared.u64 t, %1; cvt.u32.u64 %0, t; }" : "=r"(a) : "l"(p));
    return a;
}
__device__ __forceinline__ void cp16(uint32_t saddr, const void* g) {
    asm volatile("cp.async.cg.shared.global [%0], [%1], 16;" :: "r"(saddr), "l"(g));
}
__device__ __forceinline__ void cp_commit() { asm volatile("cp.async.commit_group;"); }
__device__ __forceinline__ void cp_wait0()  { asm volatile("cp.async.wait_group 0;"); }

__device__ __forceinline__ void ldsm_x4(uint32_t& r0, uint32_t& r1, uint32_t& r2, uint32_t& r3,
                                        uint32_t addr) {
    asm volatile("ldmatrix.sync.aligned.m8n8.x4.shared.b16 {%0,%1,%2,%3}, [%4];"
                 : "=r"(r0), "=r"(r1), "=r"(r2), "=r"(r3) : "r"(addr));
}
__device__ __forceinline__ void mma16816(float& c0, float& c1, float& c2, float& c3,
                                         uint32_t a0, uint32_t a1, uint32_t a2, uint32_t a3,
                                         uint32_t b0, uint32_t b1) {
    asm volatile(
        "mma.sync.aligned.m16n8k16.row.col.f32.bf16.bf16.f32 "
        "{%0,%1,%2,%3}, {%4,%5,%6,%7}, {%8,%9}, {%0,%1,%2,%3};"
        : "+f"(c0), "+f"(c1), "+f"(c2), "+f"(c3)
        : "r"(a0), "r"(a1), "r"(a2), "r"(a3), "r"(b0), "r"(b1));
}

// tile geometry
#define BM 128
#define BN 128
#define BK 32
#define ROWB   80                 // bytes per padded smem row (32 bf16 + 8 pad)
#define TILEB  (128 * ROWB)       // 10240 bytes per tile buffer

// ---------------------------------------------------------------------------
// Split-bf16x3 GEMM (NT): C[m,n] = sum_k A[m,k]*B[n,k]
//   K-segments: (Ahi,Bhi), (Alo,Bhi), (Ahi,Blo)
// CTA 128x128, BK=32, 256 thr, 8 warps (4 M x 2 N), warp tile 32x64.
// mode 0: fp32 C. mode 1: tanh(acc) split into Chi/Clo (bf16).
// ---------------------------------------------------------------------------
__global__ __launch_bounds__(256, 2) void gemm_split3(
    const __nv_bfloat16* __restrict__ Ahi, const __nv_bfloat16* __restrict__ Alo, long long sA,
    const __nv_bfloat16* __restrict__ Bhi, const __nv_bfloat16* __restrict__ Blo, long long sB,
    float* __restrict__ C, __nv_bfloat16* __restrict__ Chi, __nv_bfloat16* __restrict__ Clo,
    long long sC, int N, int K, int mode)
{
    __shared__ __align__(128) __nv_bfloat16 As[2][128][40];
    __shared__ __align__(128) __nv_bfloat16 Bs[2][128][40];

    const int t = threadIdx.x;
    const int bz = blockIdx.z;
    const int m0 = blockIdx.y * BM;
    const int n0 = blockIdx.x * BN;

    const int lane = t & 31;
    const int wid  = t >> 5;
    const int wm   = wid & 3;          // 0..3 (M)
    const int wn   = wid >> 2;         // 0..1 (N)
    const int g    = lane >> 3;        // ldmatrix tile group
    const int lr   = lane & 7;

    const uint32_t sA0 = smem_u32(&As[0][0][0]);
    const uint32_t sB0 = smem_u32(&Bs[0][0][0]);

    // ldmatrix base offsets (bytes, within one buffer)
    const uint32_t abase = (uint32_t)((wm * 32 + ((g & 1) << 3) + lr) * ROWB + ((g >> 1) << 4));
    const uint32_t bbase = (uint32_t)((wn * 64 + ((g >> 1) << 3) + lr) * ROWB + ((g & 1) << 4));

    // cp.async indices: 2 iters for A, 2 for B; row = idx>>2, seg = idx&3
    const int r0_ = t >> 2, s0_ = (t & 3);

    const __nv_bfloat16* Ah = Ahi + (size_t)bz * sA + (size_t)m0 * K;
    const __nv_bfloat16* Al = Alo + (size_t)bz * sA + (size_t)m0 * K;
    const __nv_bfloat16* Bh = Bhi + (size_t)bz * sB + (size_t)n0 * K;
    const __nv_bfloat16* Bl = Blo + (size_t)bz * sB + (size_t)n0 * K;

    const int cpk = K >> 5;           // chunks per segment
    const int nch = 3 * cpk;

    float acc[2][8][4];
    #pragma unroll
    for (int i = 0; i < 2; i++)
        #pragma unroll
        for (int j = 0; j < 8; j++)
            #pragma unroll
            for (int q = 0; q < 4; q++) acc[i][j][q] = 0.f;

    // chunk loader
    auto load_chunk = [&](int buf, int c) {
        int seg = 0, kc = c;
        if (kc >= cpk) { kc -= cpk; seg = 1; }
        if (kc >= cpk) { kc -= cpk; seg = 2; }
        const int kk = kc << 5;
        const __nv_bfloat16* pA = (seg == 1) ? Al : Ah;
        const __nv_bfloat16* pB = (seg == 2) ? Bl : Bh;
        const uint32_t sa = sA0 + buf * TILEB;
        const uint32_t sb = sB0 + buf * TILEB;
        #pragma unroll
        for (int i = 0; i < 2; i++) {
            const int row = r0_ + i * 64;
            cp16(sa + (uint32_t)(row * ROWB + s0_ * 16), pA + (size_t)row * K + kk + s0_ * 8);
        }
        #pragma unroll
        for (int i = 0; i < 2; i++) {
            const int row = r0_ + i * 64;
            cp16(sb + (uint32_t)(row * ROWB + s0_ * 16), pB + (size_t)row * K + kk + s0_ * 8);
        }
        cp_commit();
    };

    load_chunk(0, 0);

    for (int c = 0; c < nch; c++) {
        cp_wait0();
        __syncthreads();
        if (c + 1 < nch) load_chunk((c + 1) & 1, c + 1);

        const int buf = c & 1;
        const uint32_t sa = sA0 + buf * TILEB + abase;
        const uint32_t sb = sB0 + buf * TILEB + bbase;

        #pragma unroll
        for (int ks = 0; ks < 2; ks++) {
            uint32_t a[2][4];
            uint32_t b[4][4];
            #pragma unroll
            for (int mi = 0; mi < 2; mi++)
                ldsm_x4(a[mi][0], a[mi][1], a[mi][2], a[mi][3],
                        sa + (uint32_t)(mi * 16 * ROWB + ks * 32));
            #pragma unroll
            for (int p = 0; p < 4; p++)
                ldsm_x4(b[p][0], b[p][1], b[p][2], b[p][3],
                        sb + (uint32_t)(p * 16 * ROWB + ks * 32));
            #pragma unroll
            for (int mi = 0; mi < 2; mi++)
                #pragma unroll
                for (int j = 0; j < 8; j++) {
                    const int p = j >> 1, h = j & 1;
                    mma16816(acc[mi][j][0], acc[mi][j][1], acc[mi][j][2], acc[mi][j][3],
                             a[mi][0], a[mi][1], a[mi][2], a[mi][3],
                             b[p][h * 2], b[p][h * 2 + 1]);
                }
        }
        __syncthreads();
    }

    // epilogue (register -> global)
    const int rrow = lane >> 2;
    const int rcol = (lane & 3) * 2;
    #pragma unroll
    for (int mi = 0; mi < 2; mi++) {
        const int gr = m0 + wm * 32 + mi * 16 + rrow;
        #pragma unroll
        for (int j = 0; j < 8; j++) {
            const int gc = n0 + wn * 64 + j * 8 + rcol;
            const size_t o0 = (size_t)bz * sC + (size_t)gr * N + gc;
            const size_t o1 = o0 + (size_t)8 * N;
            if (mode == 0) {
                *(float2*)(C + o0) = make_float2(acc[mi][j][0], acc[mi][j][1]);
                *(float2*)(C + o1) = make_float2(acc[mi][j][2], acc[mi][j][3]);
            } else {
                #pragma unroll
                for (int h = 0; h < 2; h++) {
                    float v0 = tanhf(acc[mi][j][h * 2 + 0]);
                    float v1 = tanhf(acc[mi][j][h * 2 + 1]);
                    __nv_bfloat16 h0 = __float2bfloat16(v0);
                    __nv_bfloat16 h1 = __float2bfloat16(v1);
                    __nv_bfloat16 l0 = __float2bfloat16(v0 - __bfloat162float(h0));
                    __nv_bfloat16 l1 = __float2bfloat16(v1 - __bfloat162float(h1));
                    union { __nv_bfloat16 b[2]; uint32_t u; } H, L;
                    H.b[0] = h0; H.b[1] = h1; L.b[0] = l0; L.b[1] = l1;
                    const size_t oo = h ? o1 : o0;
                    *(uint32_t*)(Chi + oo) = H.u;
                    *(uint32_t*)(Clo + oo) = L.u;
                }
            }
        }
    }
}

// ---------------------------------------------------------------------------
// elementwise fp32 -> (hi, lo) bf16 split. one float4 per thread.
// ---------------------------------------------------------------------------
__global__ __launch_bounds__(256) void split_ew(
    const float* __restrict__ s, __nv_bfloat16* __restrict__ hi, __nv_bfloat16* __restrict__ lo)
{
    size_t i = ((size_t)blockIdx.x * 256 + threadIdx.x) * 4;
    float4 v = *(const float4*)(s + i);
    float vv[4] = {v.x, v.y, v.z, v.w};
    union { __nv_bfloat16 b[4]; uint2 u; } H, L;
    #pragma unroll
    for (int j = 0; j < 4; j++) {
        __nv_bfloat16 h = __float2bfloat16(vv[j]);
        H.b[j] = h;
        L.b[j] = __float2bfloat16(vv[j] - __bfloat162float(h));
    }
    *(uint2*)(hi + i) = H.u;
    *(uint2*)(lo + i) = L.u;
}

// ---------------------------------------------------------------------------
// per-batch transpose + split: x[b, L, D] -> xT[b, D, L] (hi/lo bf16)
// ---------------------------------------------------------------------------
__global__ __launch_bounds__(256) void transpose_split(
    const float* __restrict__ x, __nv_bfloat16* __restrict__ thi, __nv_bfloat16* __restrict__ tlo)
{
    __shared__ float tile[32][33];
    const int b = blockIdx.z;
    const float* xb = x + (size_t)b * SEQ * DIM;
    const int l0 = blockIdx.y * 32;
    const int d0 = blockIdx.x * 32;
    const int tx = threadIdx.x, ty = threadIdx.y;

    #pragma unroll
    for (int i = ty; i < 32; i += 8)
        tile[i][tx] = xb[(size_t)(l0 + i) * DIM + d0 + tx];
    __syncthreads();

    __nv_bfloat16* th = thi + (size_t)b * DIM * SEQ;
    __nv_bfloat16* tl = tlo + (size_t)b * DIM * SEQ;
    #pragma unroll
    for (int i = ty; i < 32; i += 8) {
        float v = tile[tx][i];
        __nv_bfloat16 h = __float2bfloat16(v);
        size_t o = (size_t)(d0 + i) * SEQ + l0 + tx;
        th[o] = h;
        tl[o] = __float2bfloat16(v - __bfloat162float(h));
    }
}

// ---------------------------------------------------------------------------
// row softmax in place (fp32) + emit bf16 hi/lo split.
// ---------------------------------------------------------------------------
__global__ __launch_bounds__(256) void softmax_split(
    float* __restrict__ d, __nv_bfloat16* __restrict__ ahi, __nv_bfloat16* __restrict__ alo)
{
    const size_t base = (size_t)blockIdx.x * SEQ;
    float* p = d + base;
    const int t = threadIdx.x;
    const int w = t >> 5, lane = t & 31;

    float v[8];
    float m = -1e30f;
    #pragma unroll
    for (int k = 0; k < 8; k++) { v[k] = p[t + k * 256]; m = fmaxf(m, v[k]); }
    #pragma unroll
    for (int o = 16; o; o >>= 1) m = fmaxf(m, __shfl_xor_sync(0xffffffffu, m, o));

    __shared__ float sm[8], ss[8];
    if (lane == 0) sm[w] = m;
    __syncthreads();
    float bm = sm[0];
    #pragma unroll
    for (int i = 1; i < 8; i++) bm = fmaxf(bm, sm[i]);

    float s = 0.f;
    #pragma unroll
    for (int k = 0; k < 8; k++) { v[k] = __expf(v[k] - bm); s += v[k]; }
    #pragma unroll
    for (int o = 16; o; o >>= 1) s += __shfl_xor_sync(0xffffffffu, s, o);
    if (lane == 0) ss[w] = s;
    __syncthreads();
    float bs = 0.f;
    #pragma unroll
    for (int i = 0; i < 8; i++) bs += ss[i];
    const float inv = 1.0f / bs;

    #pragma unroll
    for (int k = 0; k < 8; k++) {
        float r = v[k] * inv;
        p[t + k * 256] = r;
        __nv_bfloat16 h = __float2bfloat16(r);
        ahi[base + t + k * 256] = h;
        alo[base + t + k * 256] = __float2bfloat16(r - __bfloat162float(h));
    }
}

// ---------------------------------------------------------------------------
// weighted_output[r] = dot(ctx[r,:], W3[r % NL,:]) + b3[r % NL]
// ---------------------------------------------------------------------------
__global__ __launch_bounds__(256) void weighted_out(
    const float* __restrict__ ctx, const float* __restrict__ W3,
    const float* __restrict__ b3, float* __restrict__ out)
{
    const int r = blockIdx.x * 8 + (threadIdx.x >> 5);
    const int lane = threadIdx.x & 31;
    const int n = r & (NLDIM - 1);
    const float* c = ctx + (size_t)r * DIM;
    const float* w = W3 + (size_t)n * DIM;
    float s = 0.f;
    #pragma unroll
    for (int j = 0; j < 4; j++) {
        float4 cv = *(const float4*)(c + lane * 4 + j * 128);
        float4 wv = *(const float4*)(w + lane * 4 + j * 128);
        s += cv.x * wv.x + cv.y * wv.y + cv.z * wv.z + cv.w * wv.w;
    }
    #pragma unroll
    for (int o = 16; o; o >>= 1) s += __shfl_xor_sync(0xffffffffu, s, o);
    if (lane == 0) out[r] = s + b3[n];
}

// ---------------------------------------------------------------------------
extern "C" void kernel_launch(void* const* d_in, const int* in_sizes, int n_in,
                              void* d_out, int out_size)
{
    const float* x  = (const float*)d_in[0];
    const float* W1 = (const float*)d_in[1];
    const float* W2 = (const float*)d_in[2];
    const float* W3 = (const float*)d_in[3];
    const float* b3 = (const float*)d_in[4];

    float* ctx = (float*)d_out;                       // [B, NL, D]
    float* wo  = ctx + (size_t)BATCH * NLDIM * DIM;   // [B, NL]
    float* att = wo + (size_t)BATCH * NLDIM;          // [B, NL, L]

    __nv_bfloat16 *xhi, *xlo, *xthi, *xtlo, *whi, *wlo, *ahi, *alo, *w1hi, *w1lo, *w2hi, *w2lo;
    cudaGetSymbolAddress((void**)&xhi, g_xhi);
    cudaGetSymbolAddress((void**)&xlo, g_xlo);
    cudaGetSymbolAddress((void**)&xthi, g_xthi);
    cudaGetSymbolAddress((void**)&xtlo, g_xtlo);
    cudaGetSymbolAddress((void**)&whi, g_whi);
    cudaGetSymbolAddress((void**)&wlo, g_wlo);
    cudaGetSymbolAddress((void**)&ahi, g_ahi);
    cudaGetSymbolAddress((void**)&alo, g_alo);
    cudaGetSymbolAddress((void**)&w1hi, g_w1hi);
    cudaGetSymbolAddress((void**)&w1lo, g_w1lo);
    cudaGetSymbolAddress((void**)&w2hi, g_w2hi);
    cudaGetSymbolAddress((void**)&w2lo, g_w2lo);

    // splits
    split_ew<<<(BATCH * SEQ * DIM) / 1024, 256>>>(x, xhi, xlo);
    split_ew<<<(DADIM * DIM) / 1024, 256>>>(W1, w1hi, w1lo);
    split_ew<<<(NLDIM * DADIM) / 1024, 256>>>(W2, w2hi, w2lo);
    {
        dim3 g(DIM / 32, SEQ / 32, BATCH);
        transpose_split<<<g, dim3(32, 8)>>>(x, xthi, xtlo);
    }

    // GEMM1: w = tanh(x @ W1^T), M=B*L, N=DA, K=D; tanh-split epilogue
    {
        dim3 g(DADIM / 128, (BATCH * SEQ) / 128, 1);
        gemm_split3<<<g, 256>>>(xhi, xlo, 0, w1hi, w1lo, 0,
                                nullptr, whi, wlo, 0, DADIM, DIM, 1);
    }
    // GEMM2: logits[b,n,l] = W2 @ w[b]^T, per batch M=NL, N=L, K=DA -> att (fp32)
    {
        dim3 g(SEQ / 128, NLDIM / 128, BATCH);
        gemm_split3<<<g, 256>>>(w2hi, w2lo, 0,
                                whi, wlo, (long long)SEQ * DADIM,
                                att, nullptr, nullptr,
                                (long long)NLDIM * SEQ, SEQ, DADIM, 0);
    }
    // softmax over L in place + split
    softmax_split<<<BATCH * NLDIM, 256>>>(att, ahi, alo);

    // GEMM3: ctx[b,n,d] = att[b] @ x[b], per batch M=NL, N=D, K=L; B operand = xT
    {
        dim3 g(DIM / 128, NLDIM / 128, BATCH);
        gemm_split3<<<g, 256>>>(ahi, alo, (long long)NLDIM * SEQ,
                                xthi, xtlo, (long long)DIM * SEQ,
                                ctx, nullptr, nullptr,
                                (long long)NLDIM * DIM, DIM, SEQ, 0);
    }
    // weighted output
    weighted_out<<<(BATCH * NLDIM) / 8, 256>>>(ctx, W3, b3, wo);
}

// round 4
// speedup vs baseline: 2.7946x; 1.0859x over previous
#include <cuda_runtime.h>
#include <cuda_bf16.h>
#include <math.h>
#include <stdint.h>

#define BATCH 32
#define SEQ   2048
#define DIM   512
#define DADIM 512
#define NLDIM 512

// ---------------- split scratch (static, allocation-free) ----------------
__device__ __nv_bfloat16 g_xhi [(size_t)BATCH * SEQ * DIM];
__device__ __nv_bfloat16 g_xlo [(size_t)BATCH * SEQ * DIM];
__device__ __nv_bfloat16 g_whi [(size_t)BATCH * SEQ * DADIM]; // tanh output split
__device__ __nv_bfloat16 g_wlo [(size_t)BATCH * SEQ * DADIM];
__device__ __nv_bfloat16 g_ahi [(size_t)BATCH * NLDIM * SEQ]; // softmax output split
__device__ __nv_bfloat16 g_alo [(size_t)BATCH * NLDIM * SEQ];
__device__ __nv_bfloat16 g_w1hi[DADIM * DIM], g_w1lo[DADIM * DIM];
__device__ __nv_bfloat16 g_w2hi[NLDIM * DADIM], g_w2lo[NLDIM * DADIM];

// ---------------- PTX helpers (family-portable: no tcgen05) ----------
__device__ __forceinline__ uint32_t smem_u32(const void* p) {
    uint32_t a;
    asm("{ .reg .u64 t; cvta.to.shared.u64 t, %1; cvt.u32.u64 %0, t; }" : "=r"(a) : "l"(p));
    return a;
}
__device__ __forceinline__ void cp16(uint32_t saddr, const void* g) {
    asm volatile("cp.async.cg.shared.global [%0], [%1], 16;" :: "r"(saddr), "l"(g));
}
__device__ __forceinline__ void cp_commit() { asm volatile("cp.async.commit_group;"); }
__device__ __forceinline__ void cp_wait0()  { asm volatile("cp.async.wait_group 0;"); }
__device__ __forceinline__ void cp_wait1()  { asm volatile("cp.async.wait_group 1;"); }

__device__ __forceinline__ void ldsm_x4(uint32_t& r0, uint32_t& r1, uint32_t& r2, uint32_t& r3,
                                        uint32_t addr) {
    asm volatile("ldmatrix.sync.aligned.m8n8.x4.shared.b16 {%0,%1,%2,%3}, [%4];"
                 : "=r"(r0), "=r"(r1), "=r"(r2), "=r"(r3) : "r"(addr));
}
__device__ __forceinline__ void ldsm_x4_t(uint32_t& r0, uint32_t& r1, uint32_t& r2, uint32_t& r3,
                                          uint32_t addr) {
    asm volatile("ldmatrix.sync.aligned.m8n8.x4.trans.shared.b16 {%0,%1,%2,%3}, [%4];"
                 : "=r"(r0), "=r"(r1), "=r"(r2), "=r"(r3) : "r"(addr));
}
__device__ __forceinline__ void mma16816(float& c0, float& c1, float& c2, float& c3,
                                         uint32_t a0, uint32_t a1, uint32_t a2, uint32_t a3,
                                         uint32_t b0, uint32_t b1) {
    asm volatile(
        "mma.sync.aligned.m16n8k16.row.col.f32.bf16.bf16.f32 "
        "{%0,%1,%2,%3}, {%4,%5,%6,%7}, {%8,%9}, {%0,%1,%2,%3};"
        : "+f"(c0), "+f"(c1), "+f"(c2), "+f"(c3)
        : "r"(a0), "r"(a1), "r"(a2), "r"(a3), "r"(b0), "r"(b1));
}

// tile geometry (both kernels): CTA 128x128, BK=32, 8 warps (4M x 2N), warp 32x64
#define ROWB   80                 // A smem row bytes (32 bf16 + pad)
#define ATILE  (128 * ROWB)       // 10240
#define BROWB  272                // NN B smem row bytes (128 bf16 + pad)
#define BTILE_NN (32 * BROWB)     // 8704
#define STG_NT (ATILE + ATILE)    // 20480
#define STG_NN (ATILE + BTILE_NN) // 18944
#define SMEM_NT (3 * STG_NT)      // 61440
#define SMEM_NN (3 * STG_NN)      // 56832

// ===========================================================================
// NT split-3 GEMM: C[m,n] = sum_k A[m,k]*B[n,k];  segs (Ahi,Bhi),(Alo,Bhi),(Ahi,Blo)
// mode 0: fp32 C. mode 1: tanh(acc) split -> Chi/Clo bf16.
// ===========================================================================
__global__ __launch_bounds__(256, 2) void gemm_split3_nt(
    const __nv_bfloat16* __restrict__ Ahi, const __nv_bfloat16* __restrict__ Alo, long long sA,
    const __nv_bfloat16* __restrict__ Bhi, const __nv_bfloat16* __restrict__ Blo, long long sB,
    float* __restrict__ C, __nv_bfloat16* __restrict__ Chi, __nv_bfloat16* __restrict__ Clo,
    long long sC, int N, int K, int mode)
{
    extern __shared__ __align__(128) char smem[];
    const uint32_t s0 = smem_u32(smem);

    const int t = threadIdx.x;
    const int bz = blockIdx.z;
    const int m0 = blockIdx.y * 128;
    const int n0 = blockIdx.x * 128;

    const int lane = t & 31;
    const int wid  = t >> 5;
    const int wm   = wid & 3;
    const int wn   = wid >> 2;
    const int g    = lane >> 3;
    const int lr   = lane & 7;

    const uint32_t abase = (uint32_t)((wm * 32 + ((g & 1) << 3) + lr) * ROWB + ((g >> 1) << 4));
    const uint32_t bbase = (uint32_t)((wn * 64 + ((g >> 1) << 3) + lr) * ROWB + ((g & 1) << 4));

    const int r0_ = t >> 2, c0_ = (t & 3);

    const __nv_bfloat16* Ah = Ahi + (size_t)bz * sA + (size_t)m0 * K;
    const __nv_bfloat16* Al = Alo + (size_t)bz * sA + (size_t)m0 * K;
    const __nv_bfloat16* Bh = Bhi + (size_t)bz * sB + (size_t)n0 * K;
    const __nv_bfloat16* Bl = Blo + (size_t)bz * sB + (size_t)n0 * K;

    const int cpk = K >> 5;
    const int nch = 3 * cpk;

    float acc[2][8][4];
    #pragma unroll
    for (int i = 0; i < 2; i++)
        #pragma unroll
        for (int j = 0; j < 8; j++)
            #pragma unroll
            for (int q = 0; q < 4; q++) acc[i][j][q] = 0.f;

    auto load_chunk = [&](int c) {
        int seg = 0, kc = c;
        if (kc >= cpk) { kc -= cpk; seg = 1; }
        if (kc >= cpk) { kc -= cpk; seg = 2; }
        const int kk = kc << 5;
        const __nv_bfloat16* pA = (seg == 1) ? Al : Ah;
        const __nv_bfloat16* pB = (seg == 2) ? Bl : Bh;
        const uint32_t sa = s0 + (uint32_t)((c % 3) * STG_NT);
        const uint32_t sb = sa + ATILE;
        #pragma unroll
        for (int i = 0; i < 2; i++) {
            const int row = r0_ + i * 64;
            cp16(sa + (uint32_t)(row * ROWB + c0_ * 16), pA + (size_t)row * K + kk + c0_ * 8);
        }
        #pragma unroll
        for (int i = 0; i < 2; i++) {
            const int row = r0_ + i * 64;
            cp16(sb + (uint32_t)(row * ROWB + c0_ * 16), pB + (size_t)row * K + kk + c0_ * 8);
        }
        cp_commit();
    };

    load_chunk(0);
    load_chunk(1);

    for (int c = 0; c < nch; c++) {
        if (c + 1 < nch) cp_wait1(); else cp_wait0();
        __syncthreads();
        if (c + 2 < nch) load_chunk(c + 2);

        const uint32_t base = s0 + (uint32_t)((c % 3) * STG_NT);
        const uint32_t sa = base + abase;
        const uint32_t sb = base + ATILE + bbase;

        #pragma unroll
        for (int ks = 0; ks < 2; ks++) {
            uint32_t a[2][4];
            uint32_t b[4][4];
            #pragma unroll
            for (int mi = 0; mi < 2; mi++)
                ldsm_x4(a[mi][0], a[mi][1], a[mi][2], a[mi][3],
                        sa + (uint32_t)(mi * 16 * ROWB + ks * 32));
            #pragma unroll
            for (int p = 0; p < 4; p++)
                ldsm_x4(b[p][0], b[p][1], b[p][2], b[p][3],
                        sb + (uint32_t)(p * 16 * ROWB + ks * 32));
            #pragma unroll
            for (int mi = 0; mi < 2; mi++)
                #pragma unroll
                for (int j = 0; j < 8; j++) {
                    const int p = j >> 1, h = j & 1;
                    mma16816(acc[mi][j][0], acc[mi][j][1], acc[mi][j][2], acc[mi][j][3],
                             a[mi][0], a[mi][1], a[mi][2], a[mi][3],
                             b[p][h * 2], b[p][h * 2 + 1]);
                }
        }
    }

    const int rrow = lane >> 2;
    const int rcol = (lane & 3) * 2;
    #pragma unroll
    for (int mi = 0; mi < 2; mi++) {
        const int gr = m0 + wm * 32 + mi * 16 + rrow;
        #pragma unroll
        for (int j = 0; j < 8; j++) {
            const int gc = n0 + wn * 64 + j * 8 + rcol;
            const size_t o0 = (size_t)bz * sC + (size_t)gr * N + gc;
            const size_t o1 = o0 + (size_t)8 * N;
            if (mode == 0) {
                *(float2*)(C + o0) = make_float2(acc[mi][j][0], acc[mi][j][1]);
                *(float2*)(C + o1) = make_float2(acc[mi][j][2], acc[mi][j][3]);
            } else {
                #pragma unroll
                for (int h = 0; h < 2; h++) {
                    float v0 = tanhf(acc[mi][j][h * 2 + 0]);
                    float v1 = tanhf(acc[mi][j][h * 2 + 1]);
                    __nv_bfloat16 h0 = __float2bfloat16(v0);
                    __nv_bfloat16 h1 = __float2bfloat16(v1);
                    __nv_bfloat16 l0 = __float2bfloat16(v0 - __bfloat162float(h0));
                    __nv_bfloat16 l1 = __float2bfloat16(v1 - __bfloat162float(h1));
                    union { __nv_bfloat16 b[2]; uint32_t u; } H, L;
                    H.b[0] = h0; H.b[1] = h1; L.b[0] = l0; L.b[1] = l1;
                    const size_t oo = h ? o1 : o0;
                    *(uint32_t*)(Chi + oo) = H.u;
                    *(uint32_t*)(Clo + oo) = L.u;
                }
            }
        }
    }
}

// ===========================================================================
// NN split-3 GEMM: C[m,n] = sum_k A[m,k]*B[k,n]; B row-major [K, NB], consumed
// via ldmatrix.trans (no pre-transpose). segs (Ahi,Bhi),(Alo,Bhi),(Ahi,Blo).
// fp32 output only.
// ===========================================================================
__global__ __launch_bounds__(256, 2) void gemm_split3_nn(
    const __nv_bfloat16* __restrict__ Ahi, const __nv_bfloat16* __restrict__ Alo, long long sA,
    const __nv_bfloat16* __restrict__ Bhi, const __nv_bfloat16* __restrict__ Blo, long long sB,
    float* __restrict__ C, long long sC, int N, int NB, int K)
{
    extern __shared__ __align__(128) char smem[];
    const uint32_t s0 = smem_u32(smem);

    const int t = threadIdx.x;
    const int bz = blockIdx.z;
    const int m0 = blockIdx.y * 128;
    const int n0 = blockIdx.x * 128;

    const int lane = t & 31;
    const int wid  = t >> 5;
    const int wm   = wid & 3;
    const int wn   = wid >> 2;
    const int g    = lane >> 3;
    const int lr   = lane & 7;

    const uint32_t abase = (uint32_t)((wm * 32 + ((g & 1) << 3) + lr) * ROWB + ((g >> 1) << 4));
    // B (trans): matrix grp g -> k-row = (g&1)*8 + lr ; n-col byte = ((g>>1)*8)*2
    const uint32_t bbase = (uint32_t)(((g & 1) * 8 + lr) * BROWB + (wn * 64 + (g >> 1) * 8) * 2);

    const int ar_ = t >> 2, ac_ = (t & 3);   // A loader
    const int br_ = t >> 4, bc_ = (t & 15);  // B loader (32 rows x 16 chunks), 2 iters

    const __nv_bfloat16* Ah = Ahi + (size_t)bz * sA + (size_t)m0 * K;
    const __nv_bfloat16* Al = Alo + (size_t)bz * sA + (size_t)m0 * K;
    const __nv_bfloat16* Bh = Bhi + (size_t)bz * sB + n0;
    const __nv_bfloat16* Bl = Blo + (size_t)bz * sB + n0;

    const int cpk = K >> 5;
    const int nch = 3 * cpk;

    float acc[2][8][4];
    #pragma unroll
    for (int i = 0; i < 2; i++)
        #pragma unroll
        for (int j = 0; j < 8; j++)
            #pragma unroll
            for (int q = 0; q < 4; q++) acc[i][j][q] = 0.f;

    auto load_chunk = [&](int c) {
        int seg = 0, kc = c;
        if (kc >= cpk) { kc -= cpk; seg = 1; }
        if (kc >= cpk) { kc -= cpk; seg = 2; }
        const int kk = kc << 5;
        const __nv_bfloat16* pA = (seg == 1) ? Al : Ah;
        const __nv_bfloat16* pB = (seg == 2) ? Bl : Bh;
        const uint32_t sa = s0 + (uint32_t)((c % 3) * STG_NN);
        const uint32_t sb = sa + ATILE;
        #pragma unroll
        for (int i = 0; i < 2; i++) {
            const int row = ar_ + i * 64;
            cp16(sa + (uint32_t)(row * ROWB + ac_ * 16), pA + (size_t)row * K + kk + ac_ * 8);
        }
        #pragma unroll
        for (int i = 0; i < 2; i++) {
            const int row = br_ + i * 16;
            cp16(sb + (uint32_t)(row * BROWB + bc_ * 16),
                 pB + (size_t)(kk + row) * NB + bc_ * 8);
        }
        cp_commit();
    };

    load_chunk(0);
    load_chunk(1);

    for (int c = 0; c < nch; c++) {
        if (c + 1 < nch) cp_wait1(); else cp_wait0();
        __syncthreads();
        if (c + 2 < nch) load_chunk(c + 2);

        const uint32_t base = s0 + (uint32_t)((c % 3) * STG_NN);
        const uint32_t sa = base + abase;
        const uint32_t sb = base + ATILE + bbase;

        #pragma unroll
        for (int ks = 0; ks < 2; ks++) {
            uint32_t a[2][4];
            uint32_t b[4][4];
            #pragma unroll
            for (int mi = 0; mi < 2; mi++)
                ldsm_x4(a[mi][0], a[mi][1], a[mi][2], a[mi][3],
                        sa + (uint32_t)(mi * 16 * ROWB + ks * 32));
            #pragma unroll
            for (int p = 0; p < 4; p++)
                ldsm_x4_t(b[p][0], b[p][1], b[p][2], b[p][3],
                          sb + (uint32_t)(ks * 16 * BROWB + p * 32));
            #pragma unroll
            for (int mi = 0; mi < 2; mi++)
                #pragma unroll
                for (int j = 0; j < 8; j++) {
                    const int p = j >> 1, h = j & 1;
                    mma16816(acc[mi][j][0], acc[mi][j][1], acc[mi][j][2], acc[mi][j][3],
                             a[mi][0], a[mi][1], a[mi][2], a[mi][3],
                             b[p][h * 2], b[p][h * 2 + 1]);
                }
        }
    }

    const int rrow = lane >> 2;
    const int rcol = (lane & 3) * 2;
    #pragma unroll
    for (int mi = 0; mi < 2; mi++) {
        const int gr = m0 + wm * 32 + mi * 16 + rrow;
        #pragma unroll
        for (int j = 0; j < 8; j++) {
            const int gc = n0 + wn * 64 + j * 8 + rcol;
            const size_t o0 = (size_t)bz * sC + (size_t)gr * N + gc;
            const size_t o1 = o0 + (size_t)8 * N;
            *(float2*)(C + o0) = make_float2(acc[mi][j][0], acc[mi][j][1]);
            *(float2*)(C + o1) = make_float2(acc[mi][j][2], acc[mi][j][3]);
        }
    }
}

// ---------------------------------------------------------------------------
__global__ __launch_bounds__(256) void split_ew(
    const float* __restrict__ s, __nv_bfloat16* __restrict__ hi, __nv_bfloat16* __restrict__ lo)
{
    size_t i = ((size_t)blockIdx.x * 256 + threadIdx.x) * 4;
    float4 v = *(const float4*)(s + i);
    float vv[4] = {v.x, v.y, v.z, v.w};
    union { __nv_bfloat16 b[4]; uint2 u; } H, L;
    #pragma unroll
    for (int j = 0; j < 4; j++) {
        __nv_bfloat16 h = __float2bfloat16(vv[j]);
        H.b[j] = h;
        L.b[j] = __float2bfloat16(vv[j] - __bfloat162float(h));
    }
    *(uint2*)(hi + i) = H.u;
    *(uint2*)(lo + i) = L.u;
}

// ---------------------------------------------------------------------------
__global__ __launch_bounds__(256) void softmax_split(
    float* __restrict__ d, __nv_bfloat16* __restrict__ ahi, __nv_bfloat16* __restrict__ alo)
{
    const size_t base = (size_t)blockIdx.x * SEQ;
    float* p = d + base;
    const int t = threadIdx.x;
    const int w = t >> 5, lane = t & 31;

    float v[8];
    float m = -1e30f;
    #pragma unroll
    for (int k = 0; k < 8; k++) { v[k] = p[t + k * 256]; m = fmaxf(m, v[k]); }
    #pragma unroll
    for (int o = 16; o; o >>= 1) m = fmaxf(m, __shfl_xor_sync(0xffffffffu, m, o));

    __shared__ float sm[8], ss[8];
    if (lane == 0) sm[w] = m;
    __syncthreads();
    float bm = sm[0];
    #pragma unroll
    for (int i = 1; i < 8; i++) bm = fmaxf(bm, sm[i]);

    float s = 0.f;
    #pragma unroll
    for (int k = 0; k < 8; k++) { v[k] = __expf(v[k] - bm); s += v[k]; }
    #pragma unroll
    for (int o = 16; o; o >>= 1) s += __shfl_xor_sync(0xffffffffu, s, o);
    if (lane == 0) ss[w] = s;
    __syncthreads();
    float bs = 0.f;
    #pragma unroll
    for (int i = 0; i < 8; i++) bs += ss[i];
    const float inv = 1.0f / bs;

    #pragma unroll
    for (int k = 0; k < 8; k++) {
        float r = v[k] * inv;
        p[t + k * 256] = r;
        __nv_bfloat16 h = __float2bfloat16(r);
        ahi[base + t + k * 256] = h;
        alo[base + t + k * 256] = __float2bfloat16(r - __bfloat162float(h));
    }
}

// ---------------------------------------------------------------------------
__global__ __launch_bounds__(256) void weighted_out(
    const float* __restrict__ ctx, const float* __restrict__ W3,
    const float* __restrict__ b3, float* __restrict__ out)
{
    const int r = blockIdx.x * 8 + (threadIdx.x >> 5);
    const int lane = threadIdx.x & 31;
    const int n = r & (NLDIM - 1);
    const float* c = ctx + (size_t)r * DIM;
    const float* w = W3 + (size_t)n * DIM;
    float s = 0.f;
    #pragma unroll
    for (int j = 0; j < 4; j++) {
        float4 cv = *(const float4*)(c + lane * 4 + j * 128);
        float4 wv = *(const float4*)(w + lane * 4 + j * 128);
        s += cv.x * wv.x + cv.y * wv.y + cv.z * wv.z + cv.w * wv.w;
    }
    #pragma unroll
    for (int o = 16; o; o >>= 1) s += __shfl_xor_sync(0xffffffffu, s, o);
    if (lane == 0) out[r] = s + b3[n];
}

// ---------------------------------------------------------------------------
extern "C" void kernel_launch(void* const* d_in, const int* in_sizes, int n_in,
                              void* d_out, int out_size)
{
    const float* x  = (const float*)d_in[0];
    const float* W1 = (const float*)d_in[1];
    const float* W2 = (const float*)d_in[2];
    const float* W3 = (const float*)d_in[3];
    const float* b3 = (const float*)d_in[4];

    float* ctx = (float*)d_out;                       // [B, NL, D]
    float* wo  = ctx + (size_t)BATCH * NLDIM * DIM;   // [B, NL]
    float* att = wo + (size_t)BATCH * NLDIM;          // [B, NL, L]

    __nv_bfloat16 *xhi, *xlo, *whi, *wlo, *ahi, *alo, *w1hi, *w1lo, *w2hi, *w2lo;
    cudaGetSymbolAddress((void**)&xhi, g_xhi);
    cudaGetSymbolAddress((void**)&xlo, g_xlo);
    cudaGetSymbolAddress((void**)&whi, g_whi);
    cudaGetSymbolAddress((void**)&wlo, g_wlo);
    cudaGetSymbolAddress((void**)&ahi, g_ahi);
    cudaGetSymbolAddress((void**)&alo, g_alo);
    cudaGetSymbolAddress((void**)&w1hi, g_w1hi);
    cudaGetSymbolAddress((void**)&w1lo, g_w1lo);
    cudaGetSymbolAddress((void**)&w2hi, g_w2hi);
    cudaGetSymbolAddress((void**)&w2lo, g_w2lo);

    cudaFuncSetAttribute(gemm_split3_nt, cudaFuncAttributeMaxDynamicSharedMemorySize, SMEM_NT);
    cudaFuncSetAttribute(gemm_split3_nn, cudaFuncAttributeMaxDynamicSharedMemorySize, SMEM_NN);

    // splits
    split_ew<<<(BATCH * SEQ * DIM) / 1024, 256>>>(x, xhi, xlo);
    split_ew<<<(DADIM * DIM) / 1024, 256>>>(W1, w1hi, w1lo);
    split_ew<<<(NLDIM * DADIM) / 1024, 256>>>(W2, w2hi, w2lo);

    // GEMM1 (NT): w = tanh(x @ W1^T), M=B*L, N=DA, K=D; tanh-split epilogue
    {
        dim3 g(DADIM / 128, (BATCH * SEQ) / 128, 1);
        gemm_split3_nt<<<g, 256, SMEM_NT>>>(xhi, xlo, 0, w1hi, w1lo, 0,
                                            nullptr, whi, wlo, 0, DADIM, DIM, 1);
    }
    // GEMM2 (NT): att[b,n,l] = W2 @ w[b]^T, per batch M=NL, N=L, K=DA -> fp32
    {
        dim3 g(SEQ / 128, NLDIM / 128, BATCH);
        gemm_split3_nt<<<g, 256, SMEM_NT>>>(w2hi, w2lo, 0,
                                            whi, wlo, (long long)SEQ * DADIM,
                                            att, nullptr, nullptr,
                                            (long long)NLDIM * SEQ, SEQ, DADIM, 0);
    }
    // softmax over L in place + bf16 split
    softmax_split<<<BATCH * NLDIM, 256>>>(att, ahi, alo);

    // GEMM3 (NN): ctx[b,n,d] = att[b] @ x[b]; B = x (row-major [L, D], ldmatrix.trans)
    {
        dim3 g(DIM / 128, NLDIM / 128, BATCH);
        gemm_split3_nn<<<g, 256, SMEM_NN>>>(ahi, alo, (long long)NLDIM * SEQ,
                                            xhi, xlo, (long long)SEQ * DIM,
                                            ctx, (long long)NLDIM * DIM,
                                            DIM, DIM, SEQ);
    }
    // weighted output
    weighted_out<<<(BATCH * NLDIM) / 8, 256>>>(ctx, W3, b3, wo);
}

// round 5
// speedup vs baseline: 6.9610x; 2.4909x over previous
#include <cuda_runtime.h>
#include <cuda_fp16.h>
#include <math.h>
#include <stdint.h>

#define BATCH 32
#define SEQ   2048
#define DIM   512
#define DADIM 512
#define NLDIM 512

// ---------------- fp16 scratch (static, allocation-free) ----------------
__device__ __half g_xh [(size_t)BATCH * SEQ * DIM];
__device__ __half g_wh [(size_t)BATCH * SEQ * DADIM];  // tanh output
__device__ __half g_ah [(size_t)BATCH * NLDIM * SEQ];  // softmax output
__device__ __half g_w1h[DADIM * DIM];
__device__ __half g_w2h[NLDIM * DADIM];

// ---------------- PTX helpers (family-portable: no tcgen05) ----------
__device__ __forceinline__ uint32_t smem_u32(const void* p) {
    uint32_t a;
    asm("{ .reg .u64 t; cvta.to.shared.u64 t, %1; cvt.u32.u64 %0, t; }" : "=r"(a) : "l"(p));
    return a;
}
__device__ __forceinline__ void cp16(uint32_t saddr, const void* g) {
    asm volatile("cp.async.cg.shared.global [%0], [%1], 16;" :: "r"(saddr), "l"(g));
}
__device__ __forceinline__ void cp_commit() { asm volatile("cp.async.commit_group;"); }
__device__ __forceinline__ void cp_wait0()  { asm volatile("cp.async.wait_group 0;"); }
__device__ __forceinline__ void cp_wait2()  { asm volatile("cp.async.wait_group 2;"); }

__device__ __forceinline__ void ldsm_x4(uint32_t& r0, uint32_t& r1, uint32_t& r2, uint32_t& r3,
                                        uint32_t addr) {
    asm volatile("ldmatrix.sync.aligned.m8n8.x4.shared.b16 {%0,%1,%2,%3}, [%4];"
                 : "=r"(r0), "=r"(r1), "=r"(r2), "=r"(r3) : "r"(addr));
}
__device__ __forceinline__ void ldsm_x4_t(uint32_t& r0, uint32_t& r1, uint32_t& r2, uint32_t& r3,
                                          uint32_t addr) {
    asm volatile("ldmatrix.sync.aligned.m8n8.x4.trans.shared.b16 {%0,%1,%2,%3}, [%4];"
                 : "=r"(r0), "=r"(r1), "=r"(r2), "=r"(r3) : "r"(addr));
}
__device__ __forceinline__ void mma16816(float& c0, float& c1, float& c2, float& c3,
                                         uint32_t a0, uint32_t a1, uint32_t a2, uint32_t a3,
                                         uint32_t b0, uint32_t b1) {
    asm volatile(
        "mma.sync.aligned.m16n8k16.row.col.f32.f16.f16.f32 "
        "{%0,%1,%2,%3}, {%4,%5,%6,%7}, {%8,%9}, {%0,%1,%2,%3};"
        : "+f"(c0), "+f"(c1), "+f"(c2), "+f"(c3)
        : "r"(a0), "r"(a1), "r"(a2), "r"(a3), "r"(b0), "r"(b1));
}

// tile geometry: CTA 128x128, BK=32, 8 warps (4M x 2N), warp 32x64, 4-stage ring
#define ROWB   80                 // A/B-NT smem row bytes (32 fp16 = 64 B + 16 pad)
#define ATILE  (128 * ROWB)       // 10240
#define BROWB  272                // NN B smem row bytes (128 fp16 = 256 B + 16 pad)
#define BTILE_NN (32 * BROWB)     // 8704
#define STG_NT (ATILE + ATILE)    // 20480
#define STG_NN (ATILE + BTILE_NN) // 18944
#define SMEM_NT (4 * STG_NT)      // 81920
#define SMEM_NN (4 * STG_NN)      // 75776

// ===========================================================================
// NT fp16 GEMM: C[m,n] = sum_k A[m,k]*B[n,k]
// mode 0: fp32 C.  mode 1: tanh(acc) -> fp16 Ch.
// ===========================================================================
__global__ __launch_bounds__(256, 2) void gemm_f16_nt(
    const __half* __restrict__ A, long long sA,
    const __half* __restrict__ B, long long sB,
    float* __restrict__ C, __half* __restrict__ Ch,
    long long sC, int N, int K, int mode)
{
    extern __shared__ __align__(128) char smem[];
    const uint32_t s0 = smem_u32(smem);

    const int t = threadIdx.x;
    const int bz = blockIdx.z;
    const int m0 = blockIdx.y * 128;
    const int n0 = blockIdx.x * 128;

    const int lane = t & 31;
    const int wid  = t >> 5;
    const int wm   = wid & 3;
    const int wn   = wid >> 2;
    const int g    = lane >> 3;
    const int lr   = lane & 7;

    const uint32_t abase = (uint32_t)((wm * 32 + ((g & 1) << 3) + lr) * ROWB + ((g >> 1) << 4));
    const uint32_t bbase = (uint32_t)((wn * 64 + ((g >> 1) << 3) + lr) * ROWB + ((g & 1) << 4));

    const int r0_ = t >> 2, c0_ = (t & 3);

    const __half* Ab = A + (size_t)bz * sA + (size_t)m0 * K;
    const __half* Bb = B + (size_t)bz * sB + (size_t)n0 * K;

    const int nch = K >> 5;

    float acc[2][8][4];
    #pragma unroll
    for (int i = 0; i < 2; i++)
        #pragma unroll
        for (int j = 0; j < 8; j++)
            #pragma unroll
            for (int q = 0; q < 4; q++) acc[i][j][q] = 0.f;

    auto load_chunk = [&](int c) {
        const int kk = c << 5;
        const uint32_t sa = s0 + (uint32_t)((c & 3) * STG_NT);
        const uint32_t sb = sa + ATILE;
        #pragma unroll
        for (int i = 0; i < 2; i++) {
            const int row = r0_ + i * 64;
            cp16(sa + (uint32_t)(row * ROWB + c0_ * 16), Ab + (size_t)row * K + kk + c0_ * 8);
        }
        #pragma unroll
        for (int i = 0; i < 2; i++) {
            const int row = r0_ + i * 64;
            cp16(sb + (uint32_t)(row * ROWB + c0_ * 16), Bb + (size_t)row * K + kk + c0_ * 8);
        }
        cp_commit();
    };

    load_chunk(0);
    load_chunk(1);
    load_chunk(2);

    for (int c = 0; c < nch; c++) {
        if (c + 2 < nch) cp_wait2(); else cp_wait0();
        __syncthreads();
        if (c + 3 < nch) load_chunk(c + 3);

        const uint32_t base = s0 + (uint32_t)((c & 3) * STG_NT);
        const uint32_t sa = base + abase;
        const uint32_t sb = base + ATILE + bbase;

        #pragma unroll
        for (int ks = 0; ks < 2; ks++) {
            uint32_t a[2][4];
            uint32_t b[4][4];
            #pragma unroll
            for (int mi = 0; mi < 2; mi++)
                ldsm_x4(a[mi][0], a[mi][1], a[mi][2], a[mi][3],
                        sa + (uint32_t)(mi * 16 * ROWB + ks * 32));
            #pragma unroll
            for (int p = 0; p < 4; p++)
                ldsm_x4(b[p][0], b[p][1], b[p][2], b[p][3],
                        sb + (uint32_t)(p * 16 * ROWB + ks * 32));
            #pragma unroll
            for (int mi = 0; mi < 2; mi++)
                #pragma unroll
                for (int j = 0; j < 8; j++) {
                    const int p = j >> 1, h = j & 1;
                    mma16816(acc[mi][j][0], acc[mi][j][1], acc[mi][j][2], acc[mi][j][3],
                             a[mi][0], a[mi][1], a[mi][2], a[mi][3],
                             b[p][h * 2], b[p][h * 2 + 1]);
                }
        }
    }

    const int rrow = lane >> 2;
    const int rcol = (lane & 3) * 2;
    #pragma unroll
    for (int mi = 0; mi < 2; mi++) {
        const int gr = m0 + wm * 32 + mi * 16 + rrow;
        #pragma unroll
        for (int j = 0; j < 8; j++) {
            const int gc = n0 + wn * 64 + j * 8 + rcol;
            const size_t o0 = (size_t)bz * sC + (size_t)gr * N + gc;
            const size_t o1 = o0 + (size_t)8 * N;
            if (mode == 0) {
                *(float2*)(C + o0) = make_float2(acc[mi][j][0], acc[mi][j][1]);
                *(float2*)(C + o1) = make_float2(acc[mi][j][2], acc[mi][j][3]);
            } else {
                union { __half h[2]; uint32_t u; } P0, P1;
                P0.h[0] = __float2half_rn(tanhf(acc[mi][j][0]));
                P0.h[1] = __float2half_rn(tanhf(acc[mi][j][1]));
                P1.h[0] = __float2half_rn(tanhf(acc[mi][j][2]));
                P1.h[1] = __float2half_rn(tanhf(acc[mi][j][3]));
                *(uint32_t*)(Ch + o0) = P0.u;
                *(uint32_t*)(Ch + o1) = P1.u;
            }
        }
    }
}

// ===========================================================================
// NN fp16 GEMM: C[m,n] = sum_k A[m,k]*B[k,n]; B row-major [K, NB] via
// ldmatrix.trans. fp32 output.
// ===========================================================================
__global__ __launch_bounds__(256, 2) void gemm_f16_nn(
    const __half* __restrict__ A, long long sA,
    const __half* __restrict__ B, long long sB,
    float* __restrict__ C, long long sC, int N, int NB, int K)
{
    extern __shared__ __align__(128) char smem[];
    const uint32_t s0 = smem_u32(smem);

    const int t = threadIdx.x;
    const int bz = blockIdx.z;
    const int m0 = blockIdx.y * 128;
    const int n0 = blockIdx.x * 128;

    const int lane = t & 31;
    const int wid  = t >> 5;
    const int wm   = wid & 3;
    const int wn   = wid >> 2;
    const int g    = lane >> 3;
    const int lr   = lane & 7;

    const uint32_t abase = (uint32_t)((wm * 32 + ((g & 1) << 3) + lr) * ROWB + ((g >> 1) << 4));
    const uint32_t bbase = (uint32_t)(((g & 1) * 8 + lr) * BROWB + (wn * 64 + (g >> 1) * 8) * 2);

    const int ar_ = t >> 2, ac_ = (t & 3);
    const int br_ = t >> 4, bc_ = (t & 15);

    const __half* Ab = A + (size_t)bz * sA + (size_t)m0 * K;
    const __half* Bb = B + (size_t)bz * sB + n0;

    const int nch = K >> 5;

    float acc[2][8][4];
    #pragma unroll
    for (int i = 0; i < 2; i++)
        #pragma unroll
        for (int j = 0; j < 8; j++)
            #pragma unroll
            for (int q = 0; q < 4; q++) acc[i][j][q] = 0.f;

    auto load_chunk = [&](int c) {
        const int kk = c << 5;
        const uint32_t sa = s0 + (uint32_t)((c & 3) * STG_NN);
        const uint32_t sb = sa + ATILE;
        #pragma unroll
        for (int i = 0; i < 2; i++) {
            const int row = ar_ + i * 64;
            cp16(sa + (uint32_t)(row * ROWB + ac_ * 16), Ab + (size_t)row * K + kk + ac_ * 8);
        }
        #pragma unroll
        for (int i = 0; i < 2; i++) {
            const int row = br_ + i * 16;
            cp16(sb + (uint32_t)(row * BROWB + bc_ * 16),
                 Bb + (size_t)(kk + row) * NB + bc_ * 8);
        }
        cp_commit();
    };

    load_chunk(0);
    load_chunk(1);
    load_chunk(2);

    for (int c = 0; c < nch; c++) {
        if (c + 2 < nch) cp_wait2(); else cp_wait0();
        __syncthreads();
        if (c + 3 < nch) load_chunk(c + 3);

        const uint32_t base = s0 + (uint32_t)((c & 3) * STG_NN);
        const uint32_t sa = base + abase;
        const uint32_t sb = base + ATILE + bbase;

        #pragma unroll
        for (int ks = 0; ks < 2; ks++) {
            uint32_t a[2][4];
            uint32_t b[4][4];
            #pragma unroll
            for (int mi = 0; mi < 2; mi++)
                ldsm_x4(a[mi][0], a[mi][1], a[mi][2], a[mi][3],
                        sa + (uint32_t)(mi * 16 * ROWB + ks * 32));
            #pragma unroll
            for (int p = 0; p < 4; p++)
                ldsm_x4_t(b[p][0], b[p][1], b[p][2], b[p][3],
                          sb + (uint32_t)(ks * 16 * BROWB + p * 32));
            #pragma unroll
            for (int mi = 0; mi < 2; mi++)
                #pragma unroll
                for (int j = 0; j < 8; j++) {
                    const int p = j >> 1, h = j & 1;
                    mma16816(acc[mi][j][0], acc[mi][j][1], acc[mi][j][2], acc[mi][j][3],
                             a[mi][0], a[mi][1], a[mi][2], a[mi][3],
                             b[p][h * 2], b[p][h * 2 + 1]);
                }
        }
    }

    const int rrow = lane >> 2;
    const int rcol = (lane & 3) * 2;
    #pragma unroll
    for (int mi = 0; mi < 2; mi++) {
        const int gr = m0 + wm * 32 + mi * 16 + rrow;
        #pragma unroll
        for (int j = 0; j < 8; j++) {
            const int gc = n0 + wn * 64 + j * 8 + rcol;
            const size_t o0 = (size_t)bz * sC + (size_t)gr * N + gc;
            const size_t o1 = o0 + (size_t)8 * N;
            *(float2*)(C + o0) = make_float2(acc[mi][j][0], acc[mi][j][1]);
            *(float2*)(C + o1) = make_float2(acc[mi][j][2], acc[mi][j][3]);
        }
    }
}

// ---------------------------------------------------------------------------
// elementwise fp32 -> fp16. one float4 per thread.
// ---------------------------------------------------------------------------
__global__ __launch_bounds__(256) void cvt_ew(
    const float* __restrict__ s, __half* __restrict__ h)
{
    size_t i = ((size_t)blockIdx.x * 256 + threadIdx.x) * 4;
    float4 v = *(const float4*)(s + i);
    union { __half h[4]; uint2 u; } H;
    H.h[0] = __float2half_rn(v.x);
    H.h[1] = __float2half_rn(v.y);
    H.h[2] = __float2half_rn(v.z);
    H.h[3] = __float2half_rn(v.w);
    *(uint2*)(h + i) = H.u;
}

// ---------------------------------------------------------------------------
// row softmax in place (fp32) + emit fp16. One block per 2048-row.
// ---------------------------------------------------------------------------
__global__ __launch_bounds__(256) void softmax_h(
    float* __restrict__ d, __half* __restrict__ ah)
{
    const size_t base = (size_t)blockIdx.x * SEQ;
    float* p = d + base;
    const int t = threadIdx.x;
    const int w = t >> 5, lane = t & 31;

    float v[8];
    float m = -1e30f;
    #pragma unroll
    for (int k = 0; k < 8; k++) { v[k] = p[t + k * 256]; m = fmaxf(m, v[k]); }
    #pragma unroll
    for (int o = 16; o; o >>= 1) m = fmaxf(m, __shfl_xor_sync(0xffffffffu, m, o));

    __shared__ float sm[8], ss[8];
    if (lane == 0) sm[w] = m;
    __syncthreads();
    float bm = sm[0];
    #pragma unroll
    for (int i = 1; i < 8; i++) bm = fmaxf(bm, sm[i]);

    float s = 0.f;
    #pragma unroll
    for (int k = 0; k < 8; k++) { v[k] = __expf(v[k] - bm); s += v[k]; }
    #pragma unroll
    for (int o = 16; o; o >>= 1) s += __shfl_xor_sync(0xffffffffu, s, o);
    if (lane == 0) ss[w] = s;
    __syncthreads();
    float bs = 0.f;
    #pragma unroll
    for (int i = 0; i < 8; i++) bs += ss[i];
    const float inv = 1.0f / bs;

    #pragma unroll
    for (int k = 0; k < 8; k++) {
        float r = v[k] * inv;
        p[t + k * 256] = r;
        ah[base + t + k * 256] = __float2half_rn(r);
    }
}

// ---------------------------------------------------------------------------
// weighted_output[r] = dot(ctx[r,:], W3[r % NL,:]) + b3[r % NL]  (all fp32)
// ---------------------------------------------------------------------------
__global__ __launch_bounds__(256) void weighted_out(
    const float* __restrict__ ctx, const float* __restrict__ W3,
    const float* __restrict__ b3, float* __restrict__ out)
{
    const int r = blockIdx.x * 8 + (threadIdx.x >> 5);
    const int lane = threadIdx.x & 31;
    const int n = r & (NLDIM - 1);
    const float* c = ctx + (size_t)r * DIM;
    const float* w = W3 + (size_t)n * DIM;
    float s = 0.f;
    #pragma unroll
    for (int j = 0; j < 4; j++) {
        float4 cv = *(const float4*)(c + lane * 4 + j * 128);
        float4 wv = *(const float4*)(w + lane * 4 + j * 128);
        s += cv.x * wv.x + cv.y * wv.y + cv.z * wv.z + cv.w * wv.w;
    }
    #pragma unroll
    for (int o = 16; o; o >>= 1) s += __shfl_xor_sync(0xffffffffu, s, o);
    if (lane == 0) out[r] = s + b3[n];
}

// ---------------------------------------------------------------------------
extern "C" void kernel_launch(void* const* d_in, const int* in_sizes, int n_in,
                              void* d_out, int out_size)
{
    const float* x  = (const float*)d_in[0];
    const float* W1 = (const float*)d_in[1];
    const float* W2 = (const float*)d_in[2];
    const float* W3 = (const float*)d_in[3];
    const float* b3 = (const float*)d_in[4];

    float* ctx = (float*)d_out;                       // [B, NL, D]
    float* wo  = ctx + (size_t)BATCH * NLDIM * DIM;   // [B, NL]
    float* att = wo + (size_t)BATCH * NLDIM;          // [B, NL, L]

    __half *xh, *wh, *ah, *w1h, *w2h;
    cudaGetSymbolAddress((void**)&xh, g_xh);
    cudaGetSymbolAddress((void**)&wh, g_wh);
    cudaGetSymbolAddress((void**)&ah, g_ah);
    cudaGetSymbolAddress((void**)&w1h, g_w1h);
    cudaGetSymbolAddress((void**)&w2h, g_w2h);

    cudaFuncSetAttribute(gemm_f16_nt, cudaFuncAttributeMaxDynamicSharedMemorySize, SMEM_NT);
    cudaFuncSetAttribute(gemm_f16_nn, cudaFuncAttributeMaxDynamicSharedMemorySize, SMEM_NN);

    // fp32 -> fp16 conversions
    cvt_ew<<<(BATCH * SEQ * DIM) / 1024, 256>>>(x, xh);
    cvt_ew<<<(DADIM * DIM) / 1024, 256>>>(W1, w1h);
    cvt_ew<<<(NLDIM * DADIM) / 1024, 256>>>(W2, w2h);

    // GEMM1 (NT): w = tanh(x @ W1^T), M=B*L, N=DA, K=D; tanh epilogue -> fp16
    {
        dim3 g(DADIM / 128, (BATCH * SEQ) / 128, 1);
        gemm_f16_nt<<<g, 256, SMEM_NT>>>(xh, 0, w1h, 0,
                                         nullptr, wh, 0, DADIM, DIM, 1);
    }
    // GEMM2 (NT): att[b,n,l] = W2 @ w[b]^T, per batch M=NL, N=L, K=DA -> fp32
    {
        dim3 g(SEQ / 128, NLDIM / 128, BATCH);
        gemm_f16_nt<<<g, 256, SMEM_NT>>>(w2h, 0,
                                         wh, (long long)SEQ * DADIM,
                                         att, nullptr,
                                         (long long)NLDIM * SEQ, SEQ, DADIM, 0);
    }
    // softmax over L in place + fp16 copy
    softmax_h<<<BATCH * NLDIM, 256>>>(att, ah);

    // GEMM3 (NN): ctx[b,n,d] = att[b] @ x[b]; B = x row-major [L, D]
    {
        dim3 g(DIM / 128, NLDIM / 128, BATCH);
        gemm_f16_nn<<<g, 256, SMEM_NN>>>(ah, (long long)NLDIM * SEQ,
                                         xh, (long long)SEQ * DIM,
                                         ctx, (long long)NLDIM * DIM,
                                         DIM, DIM, SEQ);
    }
    // weighted output
    weighted_out<<<(BATCH * NLDIM) / 8, 256>>>(ctx, W3, b3, wo);
}